// round 7
// baseline (speedup 1.0000x reference)
#include <cuda_runtime.h>
#include <cuda_bf16.h>
#include <cstdint>

// LengthRegulator. Live work (predictor is dead code in the reference):
//   cum = cumsum(target_durations, axis=1)
//   padded[b,f,:] = (f < cum[b,-1]) ? x[b, upper_bound(cum[b], f), :] : 0
//   durations_out = target_durations
// B=8, T=1024, D=1024, F=8192. Output fp32: [B*F*D padded][B*T durations].
//
// R6: perfectly balanced frame-major expand. Every block writes exactly
// FRAMES frames (32KB) -> zero work-imbalance. Repeated x-row reads are
// served by L1/L2 (adjacent frames share tokens). Scan kernel also
// scatters the frame->token map.

#define LR_B 8
#define LR_T 1024
#define LR_D 1024
#define LR_F 8192
#define LR_V4 (LR_D / 4)          // 256 float4 per row
#define FRAMES 8                  // frames per expand block (uniform)
#define SLABS (LR_F / FRAMES)     // 1024 slabs per batch

__device__ int g_tok[LR_B * LR_F];   // frame -> token (-1 = invalid)

// ---------------------------------------------------------------------------
// Kernel 1: per-batch inclusive scan (warp shuffles) + frame->token scatter
// + durations pass-through.
// ---------------------------------------------------------------------------
__global__ void lr_scan_kernel(const int* __restrict__ dur,
                               float* __restrict__ dur_out) {
    __shared__ int warp_sums[32];
    __shared__ int s_total;
    const int b    = blockIdx.x;
    const int t    = threadIdx.x;
    const int lane = t & 31;
    const int wid  = t >> 5;

    const int v = dur[b * LR_T + t];
    if (dur_out) dur_out[b * LR_T + t] = (float)v;

    int s = v;
    #pragma unroll
    for (int o = 1; o < 32; o <<= 1) {
        int u = __shfl_up_sync(0xFFFFFFFFu, s, o);
        if (lane >= o) s += u;
    }
    if (lane == 31) warp_sums[wid] = s;
    __syncthreads();

    if (wid == 0) {
        int ws = warp_sums[lane];
        #pragma unroll
        for (int o = 1; o < 32; o <<= 1) {
            int u = __shfl_up_sync(0xFFFFFFFFu, ws, o);
            if (lane >= o) ws += u;
        }
        warp_sums[lane] = ws;
    }
    __syncthreads();

    const int prefix = (wid > 0) ? warp_sums[wid - 1] : 0;
    const int end    = s + prefix;
    const int start  = end - v;
    if (t == LR_T - 1) s_total = end;
    __syncthreads();
    const int total = s_total;

    // invalid frames -> -1 (each thread covers 8 frames)
    for (int f = t; f < LR_F; f += LR_T) {
        if (f >= total) g_tok[b * LR_F + f] = -1;
    }
    // valid frames: token t owns [start, end)
    for (int f = start; f < end; ++f) g_tok[b * LR_F + f] = t;
}

// ---------------------------------------------------------------------------
// Kernel 2: balanced expand. grid (SLABS, B), 256 threads; each block writes
// exactly FRAMES frames. Thread i owns float4 column i of every frame.
// ---------------------------------------------------------------------------
__global__ void __launch_bounds__(LR_V4)
lr_expand_kernel(const float* __restrict__ x,
                 float* __restrict__ out) {
    __shared__ int s_tok[FRAMES];
    const int b  = blockIdx.y;
    const int f0 = blockIdx.x * FRAMES;
    const int i  = threadIdx.x;  // 0..255

    if (i < FRAMES) s_tok[i] = g_tok[b * LR_F + f0 + i];
    __syncthreads();

    const float4* x4 = reinterpret_cast<const float4*>(x) +
                       (size_t)b * LR_T * LR_V4 + i;

    // 8 independent loads (L1-friendly: adjacent frames share tokens)
    float4 v[FRAMES];
    #pragma unroll
    for (int j = 0; j < FRAMES; ++j) {
        const int tok = s_tok[j];
        v[j] = (tok >= 0) ? __ldg(&x4[(size_t)tok * LR_V4])
                          : make_float4(0.f, 0.f, 0.f, 0.f);
    }

    // 8 streaming stores, fully coalesced, uniform per block
    float4* o = reinterpret_cast<float4*>(out) +
                ((size_t)b * LR_F + f0) * LR_V4 + i;
    #pragma unroll
    for (int j = 0; j < FRAMES; ++j) {
        __stcs(&o[(size_t)j * LR_V4], v[j]);
    }
}

extern "C" void kernel_launch(void* const* d_in, const int* in_sizes, int n_in,
                              void* d_out, int out_size) {
    const float* x   = (const float*)d_in[0];  // [B, T, D] fp32
    const int*   dur = (const int*)  d_in[1];  // [B, T] int32
    float* out = (float*)d_out;

    const long long padded_elems = (long long)LR_B * LR_F * LR_D;
    float* dur_out =
        ((long long)out_size >= padded_elems + (long long)LR_B * LR_T)
            ? out + padded_elems : nullptr;

    lr_scan_kernel<<<LR_B, LR_T>>>(dur, dur_out);

    dim3 grid(SLABS, LR_B);
    lr_expand_kernel<<<grid, LR_V4>>>(x, out);
}

// round 8
// speedup vs baseline: 1.2494x; 1.2494x over previous
#include <cuda_runtime.h>
#include <cuda_bf16.h>
#include <cstdint>

// LengthRegulator. Live work (predictor is dead code in the reference):
//   cum = cumsum(target_durations, axis=1)
//   padded[b,f,:] = (f < cum[b,-1]) ? x[b, upper_bound(cum[b], f), :] : 0
//   durations_out = target_durations
// B=8, T=1024, D=1024, F=8192. Output fp32: [B*F*D padded][B*T durations].
//
// R8: uniform 8-frame slabs (perfect balance, from R6) + register dedup of
// repeated token rows (fixes R6's L1/LSU bottleneck: ~3.5x fewer row loads).

#define LR_B 8
#define LR_T 1024
#define LR_D 1024
#define LR_F 8192
#define LR_V4 (LR_D / 4)          // 256 float4 per row
#define FRAMES 8                  // frames per expand block (uniform)
#define SLABS (LR_F / FRAMES)     // 1024 slabs per batch

__device__ int g_tok[LR_B * LR_F];   // frame -> token (-1 = invalid)

// ---------------------------------------------------------------------------
// Kernel 1: per-batch inclusive scan (warp shuffles) + frame->token scatter
// + durations pass-through.
// ---------------------------------------------------------------------------
__global__ void lr_scan_kernel(const int* __restrict__ dur,
                               float* __restrict__ dur_out) {
    __shared__ int warp_sums[32];
    __shared__ int s_total;
    const int b    = blockIdx.x;
    const int t    = threadIdx.x;
    const int lane = t & 31;
    const int wid  = t >> 5;

    const int v = dur[b * LR_T + t];
    if (dur_out) dur_out[b * LR_T + t] = (float)v;

    int s = v;
    #pragma unroll
    for (int o = 1; o < 32; o <<= 1) {
        int u = __shfl_up_sync(0xFFFFFFFFu, s, o);
        if (lane >= o) s += u;
    }
    if (lane == 31) warp_sums[wid] = s;
    __syncthreads();

    if (wid == 0) {
        int ws = warp_sums[lane];
        #pragma unroll
        for (int o = 1; o < 32; o <<= 1) {
            int u = __shfl_up_sync(0xFFFFFFFFu, ws, o);
            if (lane >= o) ws += u;
        }
        warp_sums[lane] = ws;
    }
    __syncthreads();

    const int prefix = (wid > 0) ? warp_sums[wid - 1] : 0;
    const int end    = s + prefix;
    const int start  = end - v;
    if (t == LR_T - 1) s_total = end;
    __syncthreads();
    const int total = s_total;

    // invalid frames -> -1 (each thread covers 8 frames)
    for (int f = t; f < LR_F; f += LR_T) {
        if (f >= total) g_tok[b * LR_F + f] = -1;
    }
    // valid frames: token t owns [start, end)
    for (int f = start; f < end; ++f) g_tok[b * LR_F + f] = t;
}

// ---------------------------------------------------------------------------
// Kernel 2: balanced expand with row dedup. grid (SLABS, B), 256 threads;
// each block writes exactly FRAMES frames (32KB). Tokens in a slab are
// non-decreasing -> reuse the loaded row register when the token repeats.
// ---------------------------------------------------------------------------
__global__ void __launch_bounds__(LR_V4)
lr_expand_kernel(const float* __restrict__ x,
                 float* __restrict__ out) {
    const int b  = blockIdx.y;
    const int f0 = blockIdx.x * FRAMES;
    const int i  = threadIdx.x;  // 0..255

    // Uniform token loads (one 32B sector for the whole block, L1 broadcast)
    const int* tokp = &g_tok[b * LR_F + f0];
    int tok[FRAMES];
    #pragma unroll
    for (int j = 0; j < FRAMES; ++j) tok[j] = __ldg(&tokp[j]);

    const float4* x4 = reinterpret_cast<const float4*>(x) +
                       (size_t)b * LR_T * LR_V4 + i;
    float4* o = reinterpret_cast<float4*>(out) +
                ((size_t)b * LR_F + f0) * LR_V4 + i;

    const float4 z = make_float4(0.f, 0.f, 0.f, 0.f);
    int prev = -2;       // sentinel: never matches a real token or -1
    float4 v = z;

    #pragma unroll
    for (int j = 0; j < FRAMES; ++j) {
        if (tok[j] != prev) {
            v = (tok[j] >= 0) ? __ldg(&x4[(size_t)tok[j] * LR_V4]) : z;
            prev = tok[j];
        }
        __stcs(&o[(size_t)j * LR_V4], v);
    }
}

extern "C" void kernel_launch(void* const* d_in, const int* in_sizes, int n_in,
                              void* d_out, int out_size) {
    const float* x   = (const float*)d_in[0];  // [B, T, D] fp32
    const int*   dur = (const int*)  d_in[1];  // [B, T] int32
    float* out = (float*)d_out;

    const long long padded_elems = (long long)LR_B * LR_F * LR_D;
    float* dur_out =
        ((long long)out_size >= padded_elems + (long long)LR_B * LR_T)
            ? out + padded_elems : nullptr;

    lr_scan_kernel<<<LR_B, LR_T>>>(dur, dur_out);

    dim3 grid(SLABS, LR_B);
    lr_expand_kernel<<<grid, LR_V4>>>(x, out);
}

// round 9
// speedup vs baseline: 1.3026x; 1.0427x over previous
#include <cuda_runtime.h>
#include <cuda_bf16.h>
#include <cstdint>

// LengthRegulator. Live work (predictor is dead code in the reference):
//   cum = cumsum(target_durations, axis=1)
//   padded[b,f,:] = (f < cum[b,-1]) ? x[b, upper_bound(cum[b], f), :] : 0
//   durations_out = target_durations
// B=8, T=1024, D=1024, F=8192. Output fp32: [B*F*D padded][B*T durations].
//
// R9: uniform 8-frame slabs + dedup, with INDEPENDENT predicated row loads
// (issue all boundary loads at once, one scoreboard wait) and a pure-ALU
// select chain to propagate duplicates. Removes the dependent load chain
// that capped R8 at DRAM=64%.

#define LR_B 8
#define LR_T 1024
#define LR_D 1024
#define LR_F 8192
#define LR_V4 (LR_D / 4)          // 256 float4 per row
#define FRAMES 8                  // frames per expand block (uniform)
#define SLABS (LR_F / FRAMES)     // 1024 slabs per batch

__device__ int g_tok[LR_B * LR_F];   // frame -> token (-1 = invalid)

// ---------------------------------------------------------------------------
// Kernel 1: per-batch inclusive scan (warp shuffles) + frame->token scatter
// + durations pass-through.
// ---------------------------------------------------------------------------
__global__ void lr_scan_kernel(const int* __restrict__ dur,
                               float* __restrict__ dur_out) {
    __shared__ int warp_sums[32];
    __shared__ int s_total;
    const int b    = blockIdx.x;
    const int t    = threadIdx.x;
    const int lane = t & 31;
    const int wid  = t >> 5;

    const int v = dur[b * LR_T + t];
    if (dur_out) dur_out[b * LR_T + t] = (float)v;

    int s = v;
    #pragma unroll
    for (int o = 1; o < 32; o <<= 1) {
        int u = __shfl_up_sync(0xFFFFFFFFu, s, o);
        if (lane >= o) s += u;
    }
    if (lane == 31) warp_sums[wid] = s;
    __syncthreads();

    if (wid == 0) {
        int ws = warp_sums[lane];
        #pragma unroll
        for (int o = 1; o < 32; o <<= 1) {
            int u = __shfl_up_sync(0xFFFFFFFFu, ws, o);
            if (lane >= o) ws += u;
        }
        warp_sums[lane] = ws;
    }
    __syncthreads();

    const int prefix = (wid > 0) ? warp_sums[wid - 1] : 0;
    const int end    = s + prefix;
    const int start  = end - v;
    if (t == LR_T - 1) s_total = end;
    __syncthreads();
    const int total = s_total;

    for (int f = t; f < LR_F; f += LR_T) {
        if (f >= total) g_tok[b * LR_F + f] = -1;
    }
    for (int f = start; f < end; ++f) g_tok[b * LR_F + f] = t;
}

// ---------------------------------------------------------------------------
// Kernel 2: balanced expand, independent dedup'd loads.
// grid (SLABS, B), 256 threads; each block writes exactly FRAMES frames.
// ---------------------------------------------------------------------------
__global__ void __launch_bounds__(LR_V4)
lr_expand_kernel(const float* __restrict__ x,
                 float* __restrict__ out) {
    const int b  = blockIdx.y;
    const int f0 = blockIdx.x * FRAMES;
    const int i  = threadIdx.x;  // 0..255

    // Uniform token fetches (one 32B sector per block)
    const int* tokp = &g_tok[b * LR_F + f0];
    int tok[FRAMES];
    #pragma unroll
    for (int j = 0; j < FRAMES; ++j) tok[j] = __ldg(&tokp[j]);

    const float4* x4 = reinterpret_cast<const float4*>(x) +
                       (size_t)b * LR_T * LR_V4 + i;
    float4* o = reinterpret_cast<float4*>(out) +
                ((size_t)b * LR_F + f0) * LR_V4 + i;

    const float4 z = make_float4(0.f, 0.f, 0.f, 0.f);

    // Run boundaries: load only the first frame of each token run.
    bool lead[FRAMES];
    lead[0] = true;
    #pragma unroll
    for (int j = 1; j < FRAMES; ++j) lead[j] = (tok[j] != tok[j - 1]);

    // Independent predicated loads — all issue back-to-back, one SB wait.
    float4 v[FRAMES];
    #pragma unroll
    for (int j = 0; j < FRAMES; ++j) {
        v[j] = z;
        if (lead[j] && tok[j] >= 0) v[j] = __ldg(&x4[(size_t)tok[j] * LR_V4]);
    }

    // Propagate duplicates with pure-ALU selects (no memory dependence).
    #pragma unroll
    for (int j = 1; j < FRAMES; ++j) {
        if (!lead[j]) v[j] = v[j - 1];
    }

    // Coalesced streaming stores, uniform per block.
    #pragma unroll
    for (int j = 0; j < FRAMES; ++j) {
        __stcs(&o[(size_t)j * LR_V4], v[j]);
    }
}

extern "C" void kernel_launch(void* const* d_in, const int* in_sizes, int n_in,
                              void* d_out, int out_size) {
    const float* x   = (const float*)d_in[0];  // [B, T, D] fp32
    const int*   dur = (const int*)  d_in[1];  // [B, T] int32
    float* out = (float*)d_out;

    const long long padded_elems = (long long)LR_B * LR_F * LR_D;
    float* dur_out =
        ((long long)out_size >= padded_elems + (long long)LR_B * LR_T)
            ? out + padded_elems : nullptr;

    lr_scan_kernel<<<LR_B, LR_T>>>(dur, dur_out);

    dim3 grid(SLABS, LR_B);
    lr_expand_kernel<<<grid, LR_V4>>>(x, out);
}